// round 12
// baseline (speedup 1.0000x reference)
#include <cuda_runtime.h>
#include <cuda_bf16.h>

#define NN 10000
#define RP 16
#define EE 64
#define NTT 8000
#define RR 8000
#define CC 16
#define NREL 50

// packed fp32x2 FMA (Blackwell): d = a*b + d on two packed floats
#define FMA_F32X2(acc, a2, b2) \
    asm("fma.rn.f32x2 %0, %1, %2, %0;" : "+l"(acc) : "l"(a2), "l"(b2))

// ---- static scratch (no allocations) ----
__device__ float g_T1[NREL * RP];
__device__ float g_T2[NREL * RP];
__device__ int   g_p[NTT];
__device__ float g_colsum[NN * RP];
__device__ float g_rowsum[NN * RP];
__device__ float g_h[NN * EE];
__device__ float g_P[NN * RP * CC];   // P[n][r2*16+c]

// K0: zero sums/h, init out = bias2; blocks 0..49 also build latent tables.
__global__ void k_zero(const float* __restrict__ bias2, float* __restrict__ out,
                       const float* __restrict__ w1a, const float* __restrict__ b1a,
                       const float* __restrict__ w1b, const float* __restrict__ b1b,
                       const float* __restrict__ w2a, const float* __restrict__ b2a,
                       const float* __restrict__ w2b, const float* __restrict__ b2b) {
    int i = blockIdx.x * blockDim.x + threadIdx.x;
    if (i < NN * RP) { g_colsum[i] = 0.f; g_rowsum[i] = 0.f; }
    if (i < NN * EE) g_h[i] = 0.f;
    if (i < NN * CC) out[i] = bias2[i & (CC - 1)];

    if (blockIdx.x < NREL && threadIdx.x < 32) {
        int p = blockIdx.x;
        int lane = threadIdx.x;
        float a0 = fmaxf(w1a[p * EE + lane] + b1a[lane], 0.f);
        float a1 = fmaxf(w1a[p * EE + 32 + lane] + b1a[32 + lane], 0.f);
        float c0 = fmaxf(w2a[p * EE + lane] + b2a[lane], 0.f);
        float c1 = fmaxf(w2a[p * EE + 32 + lane] + b2a[32 + lane], 0.f);
        float y1[RP], y2[RP];
#pragma unroll
        for (int r = 0; r < RP; r++) {
            y1[r] = a0 * w1b[lane * RP + r] + a1 * w1b[(lane + 32) * RP + r];
            y2[r] = c0 * w2b[lane * RP + r] + c1 * w2b[(lane + 32) * RP + r];
        }
#pragma unroll
        for (int off = 16; off >= 1; off >>= 1) {
#pragma unroll
            for (int r = 0; r < RP; r++) {
                y1[r] += __shfl_xor_sync(0xffffffffu, y1[r], off);
                y2[r] += __shfl_xor_sync(0xffffffffu, y2[r], off);
            }
        }
        float m1 = -1e30f, m2 = -1e30f;
#pragma unroll
        for (int r = 0; r < RP; r++) {
            y1[r] += b1b[r]; y2[r] += b2b[r];
            m1 = fmaxf(m1, y1[r]); m2 = fmaxf(m2, y2[r]);
        }
        float s1 = 0.f, s2 = 0.f, e1 = 0.f, e2 = 0.f;
#pragma unroll
        for (int r = 0; r < RP; r++) {
            float t1 = __expf(y1[r] - m1), t2 = __expf(y2[r] - m2);
            s1 += t1; s2 += t2;
            if (lane == r) { e1 = t1; e2 = t2; }
        }
        if (lane < RP) {
            g_T1[p * RP + lane] = e1 / s1;
            g_T2[p * RP + lane] = e2 / s2;
        }
    }
}

// K2: find p[t] (float4 scan of first 50 cols); accumulate colsum/rowsum.
__global__ void k_sums(const float* __restrict__ nhots, const int* __restrict__ hind) {
    int t = blockIdx.x * blockDim.x + threadIdx.x;
    float c0 = 0.f, r0 = 0.f;
    if (t < NTT) {
        const float4* row4 = (const float4*)(nhots + (size_t)t * RR);
        int p = 0;
#pragma unroll
        for (int j = 0; j < 12; j++) {
            float4 v = row4[j];
            if (v.x != 0.f) p = 4 * j;
            if (v.y != 0.f) p = 4 * j + 1;
            if (v.z != 0.f) p = 4 * j + 2;
            if (v.w != 0.f) p = 4 * j + 3;
        }
        {
            float4 v = row4[12];
            if (v.x != 0.f) p = 48;
            if (v.y != 0.f) p = 49;
        }
        g_p[t] = p;
        int s = hind[2 * (NTT + t)];
        int o = hind[2 * (NTT + t) + 1];
#pragma unroll
        for (int r = 0; r < RP; r++) {
            float l1 = g_T1[p * RP + r], l2 = g_T2[p * RP + r];
            int ic = o * r, ir = s * r;
            if (ic) atomicAdd(&g_colsum[ic], l1); else c0 += l1;
            if (ir) atomicAdd(&g_rowsum[ir], l2); else r0 += l2;
        }
    }
#pragma unroll
    for (int off = 16; off >= 1; off >>= 1) {
        c0 += __shfl_xor_sync(0xffffffffu, c0, off);
        r0 += __shfl_xor_sync(0xffffffffu, r0, off);
    }
    if ((threadIdx.x & 31) == 0) {
        if (c0 != 0.f) atomicAdd(&g_colsum[0], c0);
        if (r0 != 0.f) atomicAdd(&g_rowsum[0], r0);
    }
}

// K3: h[s] += (L1/colsum)*weights1_flat[o*r]. Warp per t; half-warp per r parity,
// float4 lanes -> 8 fully-unrolled iterations, 8 LDG.128 in flight per lane.
__global__ void k_hacc(const int* __restrict__ hind, const float* __restrict__ w1) {
    __shared__ float sT1[NREL * RP];
    for (int i = threadIdx.x; i < NREL * RP; i += blockDim.x) sT1[i] = g_T1[i];
    __syncthreads();
    int warp = threadIdx.x >> 5, lane = threadIdx.x & 31;
    int t = blockIdx.x * 8 + warp;
    int half = lane >> 4;
    int q = lane & 15;
    int p = g_p[t];
    int s = hind[2 * (NTT + t)];
    int o = hind[2 * (NTT + t) + 1];
    float ax = 0.f, ay = 0.f, az = 0.f, aw = 0.f;
#pragma unroll
    for (int i = 0; i < 8; i++) {
        int r = 2 * i + half;
        int idx = o * r;
        float w = __fdividef(sT1[p * RP + r], g_colsum[idx]);
        float4 v = ((const float4*)(w1 + (size_t)idx * EE))[q];
        ax += w * v.x; ay += w * v.y; az += w * v.z; aw += w * v.w;
    }
    ax += __shfl_xor_sync(0xffffffffu, ax, 16);
    ay += __shfl_xor_sync(0xffffffffu, ay, 16);
    az += __shfl_xor_sync(0xffffffffu, az, 16);
    aw += __shfl_xor_sync(0xffffffffu, aw, 16);
    if (half == 0) {
        float* dst = &g_h[s * EE + q * 4];
        atomicAdd(dst + 0, ax);
        atomicAdd(dst + 1, ay);
        atomicAdd(dst + 2, az);
        atomicAdd(dst + 3, aw);
    }
}

// K5: P = relu(h+bias1)(10000x64) @ B(64x256); B[k][r2*16+c] = weights2[r2,k,c]
// Tile 64x64, 256 threads, 4x4 microtile (cols tx, tx+16, tx+32, tx+48).
// k-quad inner loop: LDS.128 operands, f32x2 FMA, software pipeline depth 1.
union Pack4 { float4 v; unsigned long long u[2]; };
union Pack2 { unsigned long long u; float2 f; };

__global__ __launch_bounds__(256) void k_gemm(const float* __restrict__ w2,
                                              const float* __restrict__ bias1) {
    __shared__ float sA[64][68];    // [row][k], 272B row stride (16B multiple)
    __shared__ float sBT[64][68];   // [colLocal][k]
    int tid = threadIdx.x;
    int rb = blockIdx.x, cb = blockIdx.y;

    // A tile: bias+relu fused, float4 along k
    for (int idx4 = tid; idx4 < 64 * 16; idx4 += 256) {
        int r = idx4 >> 4;
        int k4 = (idx4 & 15) * 4;
        int gr = rb * 64 + r;
        float4 hv = make_float4(0.f, 0.f, 0.f, 0.f);
        if (gr < NN) {
            float4 h4 = *(const float4*)&g_h[gr * 64 + k4];
            float4 b4 = *(const float4*)&bias1[k4];
            hv.x = fmaxf(h4.x + b4.x, 0.f);
            hv.y = fmaxf(h4.y + b4.y, 0.f);
            hv.z = fmaxf(h4.z + b4.z, 0.f);
            hv.w = fmaxf(h4.w + b4.w, 0.f);
        }
        *(float4*)&sA[r][k4] = hv;
    }
    // B transposed: sBT[colL][k] = w2[(r2*64+k)*16 + c], colG = cb*64+colL
    for (int idx4 = tid; idx4 < 64 * 16; idx4 += 256) {
        int k = idx4 >> 4;
        int colL = (idx4 & 15) * 4;
        int colG = cb * 64 + colL;
        int r2 = colG >> 4, c = colG & 15;
        float4 bv = *(const float4*)&w2[((size_t)r2 * 64 + k) * 16 + c];
        sBT[colL + 0][k] = bv.x;
        sBT[colL + 1][k] = bv.y;
        sBT[colL + 2][k] = bv.z;
        sBT[colL + 3][k] = bv.w;
    }
    __syncthreads();

    int tx = tid & 15, ty = tid >> 4;
    Pack2 acc[4][4];
#pragma unroll
    for (int i = 0; i < 4; i++)
#pragma unroll
        for (int j = 0; j < 4; j++) acc[i][j].u = 0ull;

    Pack4 a[4], b[4], an[4], bn[4];
#pragma unroll
    for (int i = 0; i < 4; i++) a[i].v = *(const float4*)&sA[ty * 4 + i][0];
#pragma unroll
    for (int j = 0; j < 4; j++) b[j].v = *(const float4*)&sBT[tx + 16 * j][0];

#pragma unroll
    for (int kq = 0; kq < 16; kq++) {
        if (kq < 15) {
#pragma unroll
            for (int i = 0; i < 4; i++)
                an[i].v = *(const float4*)&sA[ty * 4 + i][4 * kq + 4];
#pragma unroll
            for (int j = 0; j < 4; j++)
                bn[j].v = *(const float4*)&sBT[tx + 16 * j][4 * kq + 4];
        }
#pragma unroll
        for (int i = 0; i < 4; i++)
#pragma unroll
            for (int j = 0; j < 4; j++) {
                FMA_F32X2(acc[i][j].u, a[i].u[0], b[j].u[0]);
                FMA_F32X2(acc[i][j].u, a[i].u[1], b[j].u[1]);
            }
#pragma unroll
        for (int i = 0; i < 4; i++) a[i] = an[i];
#pragma unroll
        for (int j = 0; j < 4; j++) b[j] = bn[j];
    }

#pragma unroll
    for (int i = 0; i < 4; i++) {
        int gr = rb * 64 + ty * 4 + i;
        if (gr < NN) {
            float* dst = &g_P[(size_t)gr * 256 + cb * 64];
#pragma unroll
            for (int j = 0; j < 4; j++)
                dst[tx + 16 * j] = acc[i][j].f.x + acc[i][j].f.y;
        }
    }
}

// K6: out[np,c] += (L2/rowsum)*P[o,r2,c]. 16 lanes (c) per t, 16 t per block.
__global__ void k_scatter(const int* __restrict__ hind, float* __restrict__ out) {
    __shared__ float sT2[NREL * RP];
    __shared__ float red[256];
    for (int i = threadIdx.x; i < NREL * RP; i += 256) sT2[i] = g_T2[i];
    __syncthreads();
    int tid = threadIdx.x;
    int tt = tid >> 4, c = tid & 15;
    int half = tt & 1;
    int t = blockIdx.x * 16 + tt;
    int p = g_p[t];
    int s = hind[2 * (NTT + t)];
    int o = hind[2 * (NTT + t) + 1];
    float w_mine = __fdividef(sT2[p * RP + c], g_rowsum[s * c]);
    const float* Po = g_P + (size_t)o * 256;
    float pv[RP];
#pragma unroll
    for (int r2 = 0; r2 < RP; r2++) pv[r2] = Po[r2 * 16 + c];

    float acc0 = 0.f;
#pragma unroll
    for (int r = 0; r < RP; r++) {
        float w = __shfl_sync(0xffffffffu, w_mine, half * 16 + r);
        int flat = s * r;
        int r2 = flat / NN;
        int np = flat - r2 * NN;
        float val = w * pv[r2];
        if (flat == 0) acc0 += val;
        else atomicAdd(&out[np * CC + c], val);
    }
    red[tid] = acc0;
    __syncthreads();
    if (tt == 0) {
        float ssum = 0.f;
#pragma unroll
        for (int i = 0; i < 16; i++) ssum += red[i * 16 + c];
        atomicAdd(&out[c], ssum);
    }
}

extern "C" void kernel_launch(void* const* d_in, const int* in_sizes, int n_in,
                              void* d_out, int out_size) {
    const float* nhots = (const float*)d_in[0];
    const float* w1a = (const float*)d_in[1];
    const float* b1a = (const float*)d_in[2];
    const float* w1b = (const float*)d_in[3];
    const float* b1b = (const float*)d_in[4];
    const float* w2a = (const float*)d_in[5];
    const float* b2a = (const float*)d_in[6];
    const float* w2b = (const float*)d_in[7];
    const float* b2b = (const float*)d_in[8];
    const float* weights1 = (const float*)d_in[9];
    const float* bias1 = (const float*)d_in[10];
    const float* weights2 = (const float*)d_in[11];
    const float* bias2 = (const float*)d_in[12];
    const int* hind = (const int*)d_in[13];
    float* out = (float*)d_out;

    k_zero<<<(NN * EE + 255) / 256, 256>>>(bias2, out, w1a, b1a, w1b, b1b,
                                           w2a, b2a, w2b, b2b);
    k_sums<<<(NTT + 255) / 256, 256>>>(nhots, hind);
    k_hacc<<<NTT / 8, 256>>>(hind, weights1);
    dim3 gg((NN + 63) / 64, 4);
    k_gemm<<<gg, 256>>>(weights2, bias1);
    k_scatter<<<NTT / 16, 256>>>(hind, out);
}

// round 14
// speedup vs baseline: 1.1405x; 1.1405x over previous
#include <cuda_runtime.h>
#include <cuda_bf16.h>

#define NN 10000
#define RP 16
#define EE 64
#define NTT 8000
#define RR 8000
#define CC 16
#define NREL 50

// packed fp32x2 FMA (Blackwell): d = a*b + d on two packed floats
#define FMA_F32X2(acc, a2, b2) \
    asm("fma.rn.f32x2 %0, %1, %2, %0;" : "+l"(acc) : "l"(a2), "l"(b2))
#define BCAST_F32X2(out, a) \
    asm("mov.b64 %0, {%1, %1};" : "=l"(out) : "r"(__float_as_uint(a)))

// ---- static scratch (no allocations) ----
__device__ float g_T1[NREL * RP];
__device__ float g_T2[NREL * RP];
__device__ int   g_p[NTT];
__device__ float g_colsum[NN * RP];
__device__ float g_rowsum[NN * RP];
__device__ float g_h[NN * EE];
__device__ float g_P[NN * RP * CC];   // P[n][r2*16+c]

// K0: zero sums/h, init out = bias2; blocks 0..49 also build latent tables.
__global__ void k_zero(const float* __restrict__ bias2, float* __restrict__ out,
                       const float* __restrict__ w1a, const float* __restrict__ b1a,
                       const float* __restrict__ w1b, const float* __restrict__ b1b,
                       const float* __restrict__ w2a, const float* __restrict__ b2a,
                       const float* __restrict__ w2b, const float* __restrict__ b2b) {
    int i = blockIdx.x * blockDim.x + threadIdx.x;
    if (i < NN * RP) { g_colsum[i] = 0.f; g_rowsum[i] = 0.f; }
    if (i < NN * EE) g_h[i] = 0.f;
    if (i < NN * CC) out[i] = bias2[i & (CC - 1)];

    if (blockIdx.x < NREL && threadIdx.x < 32) {
        int p = blockIdx.x;
        int lane = threadIdx.x;
        float a0 = fmaxf(w1a[p * EE + lane] + b1a[lane], 0.f);
        float a1 = fmaxf(w1a[p * EE + 32 + lane] + b1a[32 + lane], 0.f);
        float c0 = fmaxf(w2a[p * EE + lane] + b2a[lane], 0.f);
        float c1 = fmaxf(w2a[p * EE + 32 + lane] + b2a[32 + lane], 0.f);
        float y1[RP], y2[RP];
#pragma unroll
        for (int r = 0; r < RP; r++) {
            y1[r] = a0 * w1b[lane * RP + r] + a1 * w1b[(lane + 32) * RP + r];
            y2[r] = c0 * w2b[lane * RP + r] + c1 * w2b[(lane + 32) * RP + r];
        }
#pragma unroll
        for (int off = 16; off >= 1; off >>= 1) {
#pragma unroll
            for (int r = 0; r < RP; r++) {
                y1[r] += __shfl_xor_sync(0xffffffffu, y1[r], off);
                y2[r] += __shfl_xor_sync(0xffffffffu, y2[r], off);
            }
        }
        float m1 = -1e30f, m2 = -1e30f;
#pragma unroll
        for (int r = 0; r < RP; r++) {
            y1[r] += b1b[r]; y2[r] += b2b[r];
            m1 = fmaxf(m1, y1[r]); m2 = fmaxf(m2, y2[r]);
        }
        float s1 = 0.f, s2 = 0.f, e1 = 0.f, e2 = 0.f;
#pragma unroll
        for (int r = 0; r < RP; r++) {
            float t1 = __expf(y1[r] - m1), t2 = __expf(y2[r] - m2);
            s1 += t1; s2 += t2;
            if (lane == r) { e1 = t1; e2 = t2; }
        }
        if (lane < RP) {
            g_T1[p * RP + lane] = e1 / s1;
            g_T2[p * RP + lane] = e2 / s2;
        }
    }
}

// K2: find p[t] (float4 scan of first 50 cols); accumulate colsum/rowsum.
__global__ void k_sums(const float* __restrict__ nhots, const int* __restrict__ hind) {
    int t = blockIdx.x * blockDim.x + threadIdx.x;
    float c0 = 0.f, r0 = 0.f;
    if (t < NTT) {
        const float4* row4 = (const float4*)(nhots + (size_t)t * RR);
        int p = 0;
#pragma unroll
        for (int j = 0; j < 12; j++) {
            float4 v = row4[j];
            if (v.x != 0.f) p = 4 * j;
            if (v.y != 0.f) p = 4 * j + 1;
            if (v.z != 0.f) p = 4 * j + 2;
            if (v.w != 0.f) p = 4 * j + 3;
        }
        {
            float4 v = row4[12];
            if (v.x != 0.f) p = 48;
            if (v.y != 0.f) p = 49;
        }
        g_p[t] = p;
        int s = hind[2 * (NTT + t)];
        int o = hind[2 * (NTT + t) + 1];
#pragma unroll
        for (int r = 0; r < RP; r++) {
            float l1 = g_T1[p * RP + r], l2 = g_T2[p * RP + r];
            int ic = o * r, ir = s * r;
            if (ic) atomicAdd(&g_colsum[ic], l1); else c0 += l1;
            if (ir) atomicAdd(&g_rowsum[ir], l2); else r0 += l2;
        }
    }
#pragma unroll
    for (int off = 16; off >= 1; off >>= 1) {
        c0 += __shfl_xor_sync(0xffffffffu, c0, off);
        r0 += __shfl_xor_sync(0xffffffffu, r0, off);
    }
    if ((threadIdx.x & 31) == 0) {
        if (c0 != 0.f) atomicAdd(&g_colsum[0], c0);
        if (r0 != 0.f) atomicAdd(&g_rowsum[0], r0);
    }
}

// K3: h[s] += (L1/colsum)*weights1_flat[o*r]. Warp per t; half-warp per r parity,
// float4 lanes -> 8 fully-unrolled iterations, 8 LDG.128 in flight per lane.
__global__ void k_hacc(const int* __restrict__ hind, const float* __restrict__ w1) {
    __shared__ float sT1[NREL * RP];
    for (int i = threadIdx.x; i < NREL * RP; i += blockDim.x) sT1[i] = g_T1[i];
    __syncthreads();
    int warp = threadIdx.x >> 5, lane = threadIdx.x & 31;
    int t = blockIdx.x * 8 + warp;
    int half = lane >> 4;
    int q = lane & 15;
    int p = g_p[t];
    int s = hind[2 * (NTT + t)];
    int o = hind[2 * (NTT + t) + 1];
    float ax = 0.f, ay = 0.f, az = 0.f, aw = 0.f;
#pragma unroll
    for (int i = 0; i < 8; i++) {
        int r = 2 * i + half;
        int idx = o * r;
        float w = __fdividef(sT1[p * RP + r], g_colsum[idx]);
        float4 v = ((const float4*)(w1 + (size_t)idx * EE))[q];
        ax += w * v.x; ay += w * v.y; az += w * v.z; aw += w * v.w;
    }
    ax += __shfl_xor_sync(0xffffffffu, ax, 16);
    ay += __shfl_xor_sync(0xffffffffu, ay, 16);
    az += __shfl_xor_sync(0xffffffffu, az, 16);
    aw += __shfl_xor_sync(0xffffffffu, aw, 16);
    if (half == 0) {
        float* dst = &g_h[s * EE + q * 4];
        atomicAdd(dst + 0, ax);
        atomicAdd(dst + 1, ay);
        atomicAdd(dst + 2, az);
        atomicAdd(dst + 3, aw);
    }
}

// K5: P = relu(h+bias1)(10000x64) @ B(64x256); B[k][r2*16+c] = weights2[r2,k,c]
// Tile 64 rows x 128 cols, 256 threads, microtile 4 rows x 8 cols.
// f32x2 packed over N (col pairs): acc[i][jp] += (a_i,a_i)*(b_2jp,b_2jp+1).
// sA[64][64] + sB[64][128] = exactly 48KB static; all accesses at fixed k are
// contiguous (b) or broadcast (a) -> conflict-free.
union Pack4 { float4 v; unsigned long long u[2]; };
union Pack2 { unsigned long long u; float2 f; };

__global__ __launch_bounds__(256) void k_gemm(const float* __restrict__ w2,
                                              const float* __restrict__ bias1) {
    __shared__ float sA[64][64];     // [row][k]
    __shared__ float sB[64][128];    // [k][colLocal]
    int tid = threadIdx.x;
    int rb = blockIdx.x, cb = blockIdx.y;

    // A tile: 64 rows x 64 k, float4 along k, bias+relu fused
    for (int idx4 = tid; idx4 < 64 * 16; idx4 += 256) {
        int r = idx4 >> 4;
        int k4 = (idx4 & 15) * 4;
        int gr = rb * 64 + r;
        float4 hv = make_float4(0.f, 0.f, 0.f, 0.f);
        if (gr < NN) {
            float4 h4 = *(const float4*)&g_h[gr * 64 + k4];
            float4 b4 = *(const float4*)&bias1[k4];
            hv.x = fmaxf(h4.x + b4.x, 0.f);
            hv.y = fmaxf(h4.y + b4.y, 0.f);
            hv.z = fmaxf(h4.z + b4.z, 0.f);
            hv.w = fmaxf(h4.w + b4.w, 0.f);
        }
        *(float4*)&sA[r][k4] = hv;
    }
    // B tile: sB[k][j] = w2[(r2*64+k)*16 + c], colG = cb*128 + j
    for (int idx4 = tid; idx4 < 64 * 32; idx4 += 256) {
        int k = idx4 >> 5;
        int j4 = (idx4 & 31) * 4;
        int colG = cb * 128 + j4;
        int r2 = colG >> 4, c = colG & 15;
        float4 bv = *(const float4*)&w2[((size_t)r2 * 64 + k) * 16 + c];
        *(float4*)&sB[k][j4] = bv;
    }
    __syncthreads();

    int tx = tid & 15, ty = tid >> 4;   // rows ty*4..+3, cols {4tx..+3, 64+4tx..+3}
    Pack2 acc[4][4];
#pragma unroll
    for (int i = 0; i < 4; i++)
#pragma unroll
        for (int j = 0; j < 4; j++) acc[i][j].u = 0ull;

#pragma unroll 8
    for (int k = 0; k < 64; k++) {
        Pack4 B0, B1;
        B0.v = *(const float4*)&sB[k][4 * tx];
        B1.v = *(const float4*)&sB[k][64 + 4 * tx];
#pragma unroll
        for (int i = 0; i < 4; i++) {
            float a = sA[ty * 4 + i][k];
            unsigned long long a2;
            BCAST_F32X2(a2, a);
            FMA_F32X2(acc[i][0].u, a2, B0.u[0]);
            FMA_F32X2(acc[i][1].u, a2, B0.u[1]);
            FMA_F32X2(acc[i][2].u, a2, B1.u[0]);
            FMA_F32X2(acc[i][3].u, a2, B1.u[1]);
        }
    }

#pragma unroll
    for (int i = 0; i < 4; i++) {
        int gr = rb * 64 + ty * 4 + i;
        if (gr < NN) {
            float* dst = &g_P[(size_t)gr * 256 + cb * 128 + 4 * tx];
            *(float4*)dst = make_float4(acc[i][0].f.x, acc[i][0].f.y,
                                        acc[i][1].f.x, acc[i][1].f.y);
            *(float4*)(dst + 64) = make_float4(acc[i][2].f.x, acc[i][2].f.y,
                                               acc[i][3].f.x, acc[i][3].f.y);
        }
    }
}

// K6: out[np,c] += (L2/rowsum)*P[o,r2,c]. 16 lanes (c) per t, 16 t per block.
__global__ void k_scatter(const int* __restrict__ hind, float* __restrict__ out) {
    __shared__ float sT2[NREL * RP];
    __shared__ float red[256];
    for (int i = threadIdx.x; i < NREL * RP; i += 256) sT2[i] = g_T2[i];
    __syncthreads();
    int tid = threadIdx.x;
    int tt = tid >> 4, c = tid & 15;
    int half = tt & 1;
    int t = blockIdx.x * 16 + tt;
    int p = g_p[t];
    int s = hind[2 * (NTT + t)];
    int o = hind[2 * (NTT + t) + 1];
    float w_mine = __fdividef(sT2[p * RP + c], g_rowsum[s * c]);
    const float* Po = g_P + (size_t)o * 256;
    float pv[RP];
#pragma unroll
    for (int r2 = 0; r2 < RP; r2++) pv[r2] = Po[r2 * 16 + c];

    float acc0 = 0.f;
#pragma unroll
    for (int r = 0; r < RP; r++) {
        float w = __shfl_sync(0xffffffffu, w_mine, half * 16 + r);
        int flat = s * r;
        int r2 = flat / NN;
        int np = flat - r2 * NN;
        float val = w * pv[r2];
        if (flat == 0) acc0 += val;
        else atomicAdd(&out[np * CC + c], val);
    }
    red[tid] = acc0;
    __syncthreads();
    if (tt == 0) {
        float ssum = 0.f;
#pragma unroll
        for (int i = 0; i < 16; i++) ssum += red[i * 16 + c];
        atomicAdd(&out[c], ssum);
    }
}

extern "C" void kernel_launch(void* const* d_in, const int* in_sizes, int n_in,
                              void* d_out, int out_size) {
    const float* nhots = (const float*)d_in[0];
    const float* w1a = (const float*)d_in[1];
    const float* b1a = (const float*)d_in[2];
    const float* w1b = (const float*)d_in[3];
    const float* b1b = (const float*)d_in[4];
    const float* w2a = (const float*)d_in[5];
    const float* b2a = (const float*)d_in[6];
    const float* w2b = (const float*)d_in[7];
    const float* b2b = (const float*)d_in[8];
    const float* weights1 = (const float*)d_in[9];
    const float* bias1 = (const float*)d_in[10];
    const float* weights2 = (const float*)d_in[11];
    const float* bias2 = (const float*)d_in[12];
    const int* hind = (const int*)d_in[13];
    float* out = (float*)d_out;

    k_zero<<<(NN * EE + 255) / 256, 256>>>(bias2, out, w1a, b1a, w1b, b1b,
                                           w2a, b2a, w2b, b2b);
    k_sums<<<(NTT + 255) / 256, 256>>>(nhots, hind);
    k_hacc<<<NTT / 8, 256>>>(hind, weights1);
    dim3 gg(157, 2);
    k_gemm<<<gg, 256>>>(weights2, bias1);
    k_scatter<<<NTT / 16, 256>>>(hind, out);
}

// round 16
// speedup vs baseline: 1.2593x; 1.1042x over previous
#include <cuda_runtime.h>
#include <cuda_bf16.h>
#include <cstdint>

#define NN 10000
#define RP 16
#define EE 64
#define NTT 8000
#define RR 8000
#define CC 16
#define NREL 50

__device__ __forceinline__ uint32_t smem_u32(const void* p) {
    uint32_t a;
    asm("{ .reg .u64 t; cvta.to.shared.u64 t, %1; cvt.u32.u64 %0, t; }" : "=r"(a) : "l"(p));
    return a;
}

#define LDSM_X4(r, a) \
    asm volatile("ldmatrix.sync.aligned.m8n8.x4.shared.b16 {%0,%1,%2,%3}, [%4];" \
        : "=r"((r)[0]), "=r"((r)[1]), "=r"((r)[2]), "=r"((r)[3]) : "r"(a))
#define LDSM_X4_T(r, a) \
    asm volatile("ldmatrix.sync.aligned.m8n8.x4.trans.shared.b16 {%0,%1,%2,%3}, [%4];" \
        : "=r"((r)[0]), "=r"((r)[1]), "=r"((r)[2]), "=r"((r)[3]) : "r"(a))
#define MMA_BF16(c, a, b0, b1) \
    asm volatile("mma.sync.aligned.m16n8k16.row.col.f32.bf16.bf16.f32 " \
        "{%0,%1,%2,%3}, {%4,%5,%6,%7}, {%8,%9}, {%0,%1,%2,%3};" \
        : "+f"((c)[0]), "+f"((c)[1]), "+f"((c)[2]), "+f"((c)[3]) \
        : "r"((a)[0]), "r"((a)[1]), "r"((a)[2]), "r"((a)[3]), "r"(b0), "r"(b1))

// ---- static scratch (no allocations) ----
__device__ float g_T1[NREL * RP];
__device__ float g_T2[NREL * RP];
__device__ int   g_p[NTT];
__device__ float g_colsum[NN * RP];
__device__ float g_rowsum[NN * RP];
__device__ float g_h[NN * EE];
__device__ float g_P[NN * RP * CC];   // P[n][r2*16+c]

// K0: zero sums/h, init out = bias2; blocks 0..49 also build latent tables.
__global__ void k_zero(const float* __restrict__ bias2, float* __restrict__ out,
                       const float* __restrict__ w1a, const float* __restrict__ b1a,
                       const float* __restrict__ w1b, const float* __restrict__ b1b,
                       const float* __restrict__ w2a, const float* __restrict__ b2a,
                       const float* __restrict__ w2b, const float* __restrict__ b2b) {
    int i = blockIdx.x * blockDim.x + threadIdx.x;
    if (i < NN * RP) { g_colsum[i] = 0.f; g_rowsum[i] = 0.f; }
    if (i < NN * EE) g_h[i] = 0.f;
    if (i < NN * CC) out[i] = bias2[i & (CC - 1)];

    if (blockIdx.x < NREL && threadIdx.x < 32) {
        int p = blockIdx.x;
        int lane = threadIdx.x;
        float a0 = fmaxf(w1a[p * EE + lane] + b1a[lane], 0.f);
        float a1 = fmaxf(w1a[p * EE + 32 + lane] + b1a[32 + lane], 0.f);
        float c0 = fmaxf(w2a[p * EE + lane] + b2a[lane], 0.f);
        float c1 = fmaxf(w2a[p * EE + 32 + lane] + b2a[32 + lane], 0.f);
        float y1[RP], y2[RP];
#pragma unroll
        for (int r = 0; r < RP; r++) {
            y1[r] = a0 * w1b[lane * RP + r] + a1 * w1b[(lane + 32) * RP + r];
            y2[r] = c0 * w2b[lane * RP + r] + c1 * w2b[(lane + 32) * RP + r];
        }
#pragma unroll
        for (int off = 16; off >= 1; off >>= 1) {
#pragma unroll
            for (int r = 0; r < RP; r++) {
                y1[r] += __shfl_xor_sync(0xffffffffu, y1[r], off);
                y2[r] += __shfl_xor_sync(0xffffffffu, y2[r], off);
            }
        }
        float m1 = -1e30f, m2 = -1e30f;
#pragma unroll
        for (int r = 0; r < RP; r++) {
            y1[r] += b1b[r]; y2[r] += b2b[r];
            m1 = fmaxf(m1, y1[r]); m2 = fmaxf(m2, y2[r]);
        }
        float s1 = 0.f, s2 = 0.f, e1 = 0.f, e2 = 0.f;
#pragma unroll
        for (int r = 0; r < RP; r++) {
            float t1 = __expf(y1[r] - m1), t2 = __expf(y2[r] - m2);
            s1 += t1; s2 += t2;
            if (lane == r) { e1 = t1; e2 = t2; }
        }
        if (lane < RP) {
            g_T1[p * RP + lane] = e1 / s1;
            g_T2[p * RP + lane] = e2 / s2;
        }
    }
}

// K2: find p[t]; accumulate colsum/rowsum (index-0 hotspot pre-reduced).
__global__ void k_sums(const float* __restrict__ nhots, const int* __restrict__ hind) {
    int t = blockIdx.x * blockDim.x + threadIdx.x;
    float c0 = 0.f, r0 = 0.f;
    if (t < NTT) {
        const float4* row4 = (const float4*)(nhots + (size_t)t * RR);
        int p = 0;
#pragma unroll
        for (int j = 0; j < 12; j++) {
            float4 v = row4[j];
            if (v.x != 0.f) p = 4 * j;
            if (v.y != 0.f) p = 4 * j + 1;
            if (v.z != 0.f) p = 4 * j + 2;
            if (v.w != 0.f) p = 4 * j + 3;
        }
        {
            float4 v = row4[12];
            if (v.x != 0.f) p = 48;
            if (v.y != 0.f) p = 49;
        }
        g_p[t] = p;
        int s = hind[2 * (NTT + t)];
        int o = hind[2 * (NTT + t) + 1];
#pragma unroll
        for (int r = 0; r < RP; r++) {
            float l1 = g_T1[p * RP + r], l2 = g_T2[p * RP + r];
            int ic = o * r, ir = s * r;
            if (ic) atomicAdd(&g_colsum[ic], l1); else c0 += l1;
            if (ir) atomicAdd(&g_rowsum[ir], l2); else r0 += l2;
        }
    }
#pragma unroll
    for (int off = 16; off >= 1; off >>= 1) {
        c0 += __shfl_xor_sync(0xffffffffu, c0, off);
        r0 += __shfl_xor_sync(0xffffffffu, r0, off);
    }
    if ((threadIdx.x & 31) == 0) {
        if (c0 != 0.f) atomicAdd(&g_colsum[0], c0);
        if (r0 != 0.f) atomicAdd(&g_rowsum[0], r0);
    }
}

// K3: h[s] += (L1/colsum)*weights1_flat[o*r]. Warp per t.
__global__ void k_hacc(const int* __restrict__ hind, const float* __restrict__ w1) {
    __shared__ float sT1[NREL * RP];
    for (int i = threadIdx.x; i < NREL * RP; i += blockDim.x) sT1[i] = g_T1[i];
    __syncthreads();
    int warp = threadIdx.x >> 5, lane = threadIdx.x & 31;
    int t = blockIdx.x * 8 + warp;
    int half = lane >> 4;
    int q = lane & 15;
    int p = g_p[t];
    int s = hind[2 * (NTT + t)];
    int o = hind[2 * (NTT + t) + 1];
    float ax = 0.f, ay = 0.f, az = 0.f, aw = 0.f;
#pragma unroll
    for (int i = 0; i < 8; i++) {
        int r = 2 * i + half;
        int idx = o * r;
        float w = __fdividef(sT1[p * RP + r], g_colsum[idx]);
        float4 v = ((const float4*)(w1 + (size_t)idx * EE))[q];
        ax += w * v.x; ay += w * v.y; az += w * v.z; aw += w * v.w;
    }
    ax += __shfl_xor_sync(0xffffffffu, ax, 16);
    ay += __shfl_xor_sync(0xffffffffu, ay, 16);
    az += __shfl_xor_sync(0xffffffffu, az, 16);
    aw += __shfl_xor_sync(0xffffffffu, aw, 16);
    if (half == 0) {
        float* dst = &g_h[s * EE + q * 4];
        atomicAdd(dst + 0, ax);
        atomicAdd(dst + 1, ay);
        atomicAdd(dst + 2, az);
        atomicAdd(dst + 3, aw);
    }
}

// K5: P = relu(h+bias1)(10000x64) @ B(64x256) via mma.sync bf16-split HMMA.
// Block 256 thr = 8 warps: warp (rw = w>>2, cw = w&3) owns rows rw*16..+15,
// cols cw*64..+63 (8 n-tiles). Tile M=32, N=256, K=64; 4 k-steps of k16.
// D = Ahi*Bhi + Ahi*Blo + Alo*Bhi, fp32 accum (bf16 Markidis split).
// smem: A [m][k] bf16 (128B rows), B [k][n] bf16 (512B rows), both swizzled
// by ((row&7)<<4) so ldmatrix (A: normal, B: trans) is conflict-free.
#define SMB_A_HI 0
#define SMB_A_LO 4096
#define SMB_B_HI 8192
#define SMB_B_LO (8192 + 32768)
#define SM_TOTAL (8192 + 65536)

__global__ __launch_bounds__(256) void k_gemm(const float* __restrict__ w2,
                                              const float* __restrict__ bias1) {
    extern __shared__ char sm[];
    uint32_t base = smem_u32(sm);
    int tid = threadIdx.x;
    int rb = blockIdx.x;

    // ---- B tiles: w2 idx = (r2*64+k)*16+c -> row k, col n = r2*16+c
    for (int pp = tid; pp < 8192; pp += 256) {
        int idx = pp * 2;
        int c = idx & 15;
        int k = (idx >> 4) & 63;
        int r2 = idx >> 10;
        int n = r2 * 16 + c;
        float2 v = *(const float2*)&w2[idx];
        __nv_bfloat16 h0 = __float2bfloat16(v.x);
        __nv_bfloat16 h1 = __float2bfloat16(v.y);
        __nv_bfloat16 l0 = __float2bfloat16(v.x - __bfloat162float(h0));
        __nv_bfloat16 l1 = __float2bfloat16(v.y - __bfloat162float(h1));
        uint32_t hi = (uint32_t)*(uint16_t*)&h0 | ((uint32_t)*(uint16_t*)&h1 << 16);
        uint32_t lo = (uint32_t)*(uint16_t*)&l0 | ((uint32_t)*(uint16_t*)&l1 << 16);
        uint32_t off = (uint32_t)(k * 512) + (((uint32_t)(2 * n)) ^ ((uint32_t)(k & 7) << 4));
        *(uint32_t*)(sm + SMB_B_HI + off) = hi;
        *(uint32_t*)(sm + SMB_B_LO + off) = lo;
    }

    // ---- A tile: 32 rows, relu(h+bias1) fused; 8 threads per row, 8 k each
    {
        int r = tid >> 3;
        int kq = (tid & 7) * 8;
        int m = rb * 32 + r;
        float vv[8];
        if (m < NN) {
            float4 x0 = *(const float4*)&g_h[m * 64 + kq];
            float4 x1 = *(const float4*)&g_h[m * 64 + kq + 4];
            float4 b0 = *(const float4*)&bias1[kq];
            float4 b1 = *(const float4*)&bias1[kq + 4];
            vv[0] = fmaxf(x0.x + b0.x, 0.f); vv[1] = fmaxf(x0.y + b0.y, 0.f);
            vv[2] = fmaxf(x0.z + b0.z, 0.f); vv[3] = fmaxf(x0.w + b0.w, 0.f);
            vv[4] = fmaxf(x1.x + b1.x, 0.f); vv[5] = fmaxf(x1.y + b1.y, 0.f);
            vv[6] = fmaxf(x1.z + b1.z, 0.f); vv[7] = fmaxf(x1.w + b1.w, 0.f);
        } else {
#pragma unroll
            for (int e = 0; e < 8; e++) vv[e] = 0.f;
        }
#pragma unroll
        for (int pj = 0; pj < 4; pj++) {
            int k = kq + 2 * pj;
            __nv_bfloat16 h0 = __float2bfloat16(vv[2 * pj]);
            __nv_bfloat16 h1 = __float2bfloat16(vv[2 * pj + 1]);
            __nv_bfloat16 l0 = __float2bfloat16(vv[2 * pj] - __bfloat162float(h0));
            __nv_bfloat16 l1 = __float2bfloat16(vv[2 * pj + 1] - __bfloat162float(h1));
            uint32_t hi = (uint32_t)*(uint16_t*)&h0 | ((uint32_t)*(uint16_t*)&h1 << 16);
            uint32_t lo = (uint32_t)*(uint16_t*)&l0 | ((uint32_t)*(uint16_t*)&l1 << 16);
            uint32_t off = (uint32_t)(r * 128) + (((uint32_t)(2 * k)) ^ ((uint32_t)(r & 7) << 4));
            *(uint32_t*)(sm + SMB_A_HI + off) = hi;
            *(uint32_t*)(sm + SMB_A_LO + off) = lo;
        }
    }
    __syncthreads();

    int wid = tid >> 5, lane = tid & 31;
    int rw = wid >> 2, cw = wid & 3;
    int mbase = rw * 16;
    int g = lane >> 3, i = lane & 7;

    float acc[8][4];
#pragma unroll
    for (int nt = 0; nt < 8; nt++)
#pragma unroll
        for (int e = 0; e < 4; e++) acc[nt][e] = 0.f;

#pragma unroll
    for (int ks = 0; ks < 4; ks++) {
        int k0 = ks * 16;
        // A fragments (hi, lo): x4 groups = {m0-7,k0-7},{m8-15,k0-7},{m0-7,k8-15},{m8-15,k8-15}
        uint32_t arow = (uint32_t)(mbase + (g & 1) * 8 + i);
        uint32_t abyte = (uint32_t)(k0 * 2 + (g >> 1) * 16);
        uint32_t aoff = arow * 128 + (abyte ^ ((arow & 7) << 4));
        uint32_t ah[4], al[4];
        LDSM_X4(ah, base + SMB_A_HI + aoff);
        LDSM_X4(al, base + SMB_A_LO + aoff);
#pragma unroll
        for (int tp = 0; tp < 4; tp++) {
            int n0 = cw * 64 + tp * 16;
            // B trans x4 groups = {k0-7,n0},{k8-15,n0},{k0-7,n0+8},{k8-15,n0+8}
            uint32_t krow = (uint32_t)(k0 + (g & 1) * 8 + i);
            uint32_t nbyte = (uint32_t)((n0 + (g >> 1) * 8) * 2);
            uint32_t boff = krow * 512 + (nbyte ^ ((krow & 7) << 4));
            uint32_t bh[4], bl[4];
            LDSM_X4_T(bh, base + SMB_B_HI + boff);
            LDSM_X4_T(bl, base + SMB_B_LO + boff);
            MMA_BF16(acc[2 * tp],     ah, bh[0], bh[1]);
            MMA_BF16(acc[2 * tp + 1], ah, bh[2], bh[3]);
            MMA_BF16(acc[2 * tp],     ah, bl[0], bl[1]);
            MMA_BF16(acc[2 * tp + 1], ah, bl[2], bl[3]);
            MMA_BF16(acc[2 * tp],     al, bh[0], bh[1]);
            MMA_BF16(acc[2 * tp + 1], al, bh[2], bh[3]);
        }
    }

    // Epilogue: c0,c1 -> (row lane/4, cols 2*(lane&3)+{0,1}); c2,c3 -> row+8.
    {
        int r0 = rb * 32 + mbase + (lane >> 2);
        int cb0 = cw * 64 + 2 * (lane & 3);
#pragma unroll
        for (int nt = 0; nt < 8; nt++) {
            int col = cb0 + nt * 8;
            if (r0 < NN)
                *(float2*)&g_P[(size_t)r0 * 256 + col] = make_float2(acc[nt][0], acc[nt][1]);
            if (r0 + 8 < NN)
                *(float2*)&g_P[(size_t)(r0 + 8) * 256 + col] = make_float2(acc[nt][2], acc[nt][3]);
        }
    }
}

// K6: out[np,c] += (L2/rowsum)*P[o,r2,c]. 16 lanes (c) per t, 16 t per block.
__global__ void k_scatter(const int* __restrict__ hind, float* __restrict__ out) {
    __shared__ float sT2[NREL * RP];
    __shared__ float red[256];
    for (int i = threadIdx.x; i < NREL * RP; i += 256) sT2[i] = g_T2[i];
    __syncthreads();
    int tid = threadIdx.x;
    int tt = tid >> 4, c = tid & 15;
    int half = tt & 1;
    int t = blockIdx.x * 16 + tt;
    int p = g_p[t];
    int s = hind[2 * (NTT + t)];
    int o = hind[2 * (NTT + t) + 1];
    float w_mine = __fdividef(sT2[p * RP + c], g_rowsum[s * c]);
    const float* Po = g_P + (size_t)o * 256;
    float pv[RP];
#pragma unroll
    for (int r2 = 0; r2 < RP; r2++) pv[r2] = Po[r2 * 16 + c];

    float acc0 = 0.f;
#pragma unroll
    for (int r = 0; r < RP; r++) {
        float w = __shfl_sync(0xffffffffu, w_mine, half * 16 + r);
        int flat = s * r;
        int r2 = flat / NN;
        int np = flat - r2 * NN;
        float val = w * pv[r2];
        if (flat == 0) acc0 += val;
        else atomicAdd(&out[np * CC + c], val);
    }
    red[tid] = acc0;
    __syncthreads();
    if (tt == 0) {
        float ssum = 0.f;
#pragma unroll
        for (int i = 0; i < 16; i++) ssum += red[i * 16 + c];
        atomicAdd(&out[c], ssum);
    }
}

extern "C" void kernel_launch(void* const* d_in, const int* in_sizes, int n_in,
                              void* d_out, int out_size) {
    const float* nhots = (const float*)d_in[0];
    const float* w1a = (const float*)d_in[1];
    const float* b1a = (const float*)d_in[2];
    const float* w1b = (const float*)d_in[3];
    const float* b1b = (const float*)d_in[4];
    const float* w2a = (const float*)d_in[5];
    const float* b2a = (const float*)d_in[6];
    const float* w2b = (const float*)d_in[7];
    const float* b2b = (const float*)d_in[8];
    const float* weights1 = (const float*)d_in[9];
    const float* bias1 = (const float*)d_in[10];
    const float* weights2 = (const float*)d_in[11];
    const float* bias2 = (const float*)d_in[12];
    const int* hind = (const int*)d_in[13];
    float* out = (float*)d_out;

    cudaFuncSetAttribute(k_gemm, cudaFuncAttributeMaxDynamicSharedMemorySize, SM_TOTAL);

    k_zero<<<(NN * EE + 255) / 256, 256>>>(bias2, out, w1a, b1a, w1b, b1b,
                                           w2a, b2a, w2b, b2b);
    k_sums<<<(NTT + 255) / 256, 256>>>(nhots, hind);
    k_hacc<<<NTT / 8, 256>>>(hind, weights1);
    k_gemm<<<(NN + 31) / 32, 256, SM_TOTAL>>>(weights2, bias1);
    k_scatter<<<NTT / 16, 256>>>(hind, out);
}